// round 14
// baseline (speedup 1.0000x reference)
#include <cuda_runtime.h>
#include <cstdint>
#include <math.h>

// Problem constants: B=4, N=4096, C=1024, h=16, d=64 ; M = 16384, K = 1024
#define BM 256
#define BN 128
#define BK 16
#define STAGES 3
#define LDA 20                       // BK + 4 pad (floats); 80B row stride
#define SMEM_GEMM (STAGES * (BM + BN) * LDA * 4)

// attn_out smem: kv 64x64 + ksum 64 + 8 warps x (64x32) q-transpose
#define AO_SMEM ((4096 + 64 + 8 * 2048) * 4)

// Scratch (static __device__ globals; no allocations allowed)
__device__ float g_qkv[50331648];   // [16384, 3072]  (q|k|v), phi applied to q,k
__device__ float g_attn[16777216];  // [16384, 1024]
__device__ float g_kv_part[2097152];// [8][64][64][64]
__device__ float g_ks_part[32768];  // [8][64][64]
__device__ float g_kv[262144];      // [64][64][64]
__device__ float g_ks[4096];        // [64][64]

// ---------------------------------------------------------------------------
// PTX helpers (sm_80-baseline ISA only; target is plain sm_100)
// ---------------------------------------------------------------------------
static __device__ __forceinline__ void cp_async16(float* s, const float* g) {
    unsigned int sa = (unsigned int)__cvta_generic_to_shared(s);
    asm volatile("cp.async.cg.shared.global [%0], [%1], 16;\n" :: "r"(sa), "l"(g));
}
#define CP_COMMIT() asm volatile("cp.async.commit_group;\n" ::)
#define CP_WAIT(n)  asm volatile("cp.async.wait_group %0;\n" :: "n"(n))

static __device__ __forceinline__ void ldsm4(uint32_t r[4], const float* p) {
    unsigned int sa = (unsigned int)__cvta_generic_to_shared(p);
    asm volatile("ldmatrix.sync.aligned.m8n8.x4.shared.b16 {%0,%1,%2,%3}, [%4];"
                 : "=r"(r[0]), "=r"(r[1]), "=r"(r[2]), "=r"(r[3]) : "r"(sa));
}
static __device__ __forceinline__ void cvt_tf32(uint32_t& x) {
    asm volatile("cvt.rna.tf32.f32 %0, %0;" : "+r"(x));
}
static __device__ __forceinline__ void mma16n8k8(
    float d[4], const uint32_t a[4], uint32_t b0, uint32_t b1)
{
    asm volatile(
        "mma.sync.aligned.m16n8k8.row.col.f32.tf32.tf32.f32 "
        "{%0,%1,%2,%3}, {%4,%5,%6,%7}, {%8,%9}, {%0,%1,%2,%3};"
        : "+f"(d[0]), "+f"(d[1]), "+f"(d[2]), "+f"(d[3])
        : "r"(a[0]), "r"(a[1]), "r"(a[2]), "r"(a[3]), "r"(b0), "r"(b1));
}

// ---------------------------------------------------------------------------
// TF32 mma.sync GEMM, 3-stage cp.async pipeline, ldmatrix operand loads.
// C[m,n] = sum_k A[m,k]*W[n,k] (+bias[n]) (+phi if n0<2048)
// 256x128 CTA tile, 256 threads (8 warps: 4M x 2N), warp tile 64x64.
// ---------------------------------------------------------------------------
template <bool DO_PHI, bool DO_BIAS>
__global__ __launch_bounds__(256, 1) void gemm_tf32(
    const float* __restrict__ A, const float* __restrict__ W,
    const float* __restrict__ bias, float* __restrict__ C,
    int M, int N, int K)
{
    extern __shared__ float smem[];
    float* As = smem;                         // [STAGES][BM*LDA]
    float* Bs = smem + STAGES * BM * LDA;     // [STAGES][BN*LDA]
    __shared__ float bias_sm[BN];

    const int t  = threadIdx.x;
    const int n0 = blockIdx.x * BN;
    const int m0 = blockIdx.y * BM;
    const int warp = t >> 5;
    const int lane = t & 31;
    const int wm = warp & 3;       // 64 rows each
    const int wn = warp >> 2;      // 64 cols each
    const int lr = lane & 7;       // ldmatrix row within group
    const int lg = lane >> 3;      // ldmatrix group 0..3

    const float* Ablk = A + (size_t)m0 * K;
    const float* Wblk = W + (size_t)n0 * K;

    if (DO_BIAS && t < BN) bias_sm[t] = bias[n0 + t];

    // cp.async slots: A tile 256x16 = 1024 float4 (4/thread); B tile 512 (2/thread)
    int rrA[4], ccA[4], rrB[2], ccB[2];
    #pragma unroll
    for (int i = 0; i < 4; i++) {
        int slot = t + 256 * i;
        rrA[i] = slot >> 2;
        ccA[i] = (slot & 3) * 4;
    }
    #pragma unroll
    for (int i = 0; i < 2; i++) {
        int slot = t + 256 * i;
        rrB[i] = slot >> 2;
        ccB[i] = (slot & 3) * 4;
    }

    auto stage_load = [&](int kt, int s) {
        const int k0 = kt * BK;
        float* as = As + s * BM * LDA;
        float* bs = Bs + s * BN * LDA;
        #pragma unroll
        for (int i = 0; i < 4; i++)
            cp_async16(as + rrA[i] * LDA + ccA[i], Ablk + (size_t)rrA[i] * K + k0 + ccA[i]);
        #pragma unroll
        for (int i = 0; i < 2; i++)
            cp_async16(bs + rrB[i] * LDA + ccB[i], Wblk + (size_t)rrB[i] * K + k0 + ccB[i]);
    };

    const int nk = K / BK;
    #pragma unroll
    for (int s = 0; s < STAGES - 1; s++) {
        stage_load(s, s);
        CP_COMMIT();
    }

    float d[4][8][4];
    #pragma unroll
    for (int i = 0; i < 4; i++)
        #pragma unroll
        for (int j = 0; j < 8; j++)
            #pragma unroll
            for (int e = 0; e < 4; e++) d[i][j][e] = 0.0f;

    //  A frag i at (wm*64 + i*16, kk): row = +lr + (lg&1)*8 ; col = kk + (lg>>1)*4
    //  B pair j at (wn*64 + j*16, kk): row = +lr + (lg>>1)*8 ; col = kk + (lg&1)*4
    const int a_row = wm * 64 + lr + (lg & 1) * 8;
    const int a_col = (lg >> 1) * 4;
    const int b_row = wn * 64 + lr + (lg >> 1) * 8;
    const int b_col = (lg & 1) * 4;

    for (int kt = 0; kt < nk; ++kt) {
        CP_WAIT(STAGES - 2);
        __syncthreads();

        const int nxt = kt + STAGES - 1;
        if (nxt < nk) stage_load(nxt, nxt % STAGES);
        CP_COMMIT();

        const float* as = As + (kt % STAGES) * BM * LDA;
        const float* bs = Bs + (kt % STAGES) * BN * LDA;

        #pragma unroll
        for (int kk = 0; kk < BK; kk += 8) {
            uint32_t a[4][4], b[4][4];
            #pragma unroll
            for (int i = 0; i < 4; i++) {
                ldsm4(a[i], as + (a_row + i * 16) * LDA + kk + a_col);
                #pragma unroll
                for (int e = 0; e < 4; e++) cvt_tf32(a[i][e]);
            }
            #pragma unroll
            for (int j = 0; j < 4; j++) {
                ldsm4(b[j], bs + (b_row + j * 16) * LDA + kk + b_col);
                #pragma unroll
                for (int e = 0; e < 4; e++) cvt_tf32(b[j][e]);
            }
            #pragma unroll
            for (int i = 0; i < 4; i++)
                #pragma unroll
                for (int jj = 0; jj < 8; jj++)
                    mma16n8k8(d[i][jj], a[i],
                              b[jj >> 1][(jj & 1) * 2], b[jj >> 1][(jj & 1) * 2 + 1]);
        }
        __syncthreads();
    }

    // ---- epilogue: direct register->global stores ----
    const bool phi = DO_PHI && (n0 < 2048);
    const int er = lane >> 2;            // row within frag (0..7)
    const int ec = (lane & 3) * 2;       // col within n8 (0,2,4,6)
    #pragma unroll
    for (int i = 0; i < 4; i++) {
        const int grow = m0 + wm * 64 + i * 16 + er;
        #pragma unroll
        for (int jj = 0; jj < 8; jj++) {
            const int lcol = wn * 64 + jj * 8 + ec;
            float v[4];
            #pragma unroll
            for (int e = 0; e < 4; e++) v[e] = d[i][jj][e];
            if (phi) {
                #pragma unroll
                for (int e = 0; e < 4; e++) v[e] = expf(-0.5f * v[e] * v[e]);
            }
            if (DO_BIAS) {
                v[0] += bias_sm[lcol];     v[1] += bias_sm[lcol + 1];
                v[2] += bias_sm[lcol];     v[3] += bias_sm[lcol + 1];
            }
            *(float2*)(C + (size_t)grow * N + n0 + lcol) = make_float2(v[0], v[1]);
            *(float2*)(C + (size_t)(grow + 8) * N + n0 + lcol) = make_float2(v[2], v[3]);
        }
    }
}

// ---------------------------------------------------------------------------
// kv partials: kv[b,h,d,e] = sum_n phiK * V  (8 sequence chunks) + k_sum.
// ---------------------------------------------------------------------------
__global__ __launch_bounds__(256) void kv_partial_kernel(
    const float* __restrict__ qkv, float* __restrict__ kv_part,
    float* __restrict__ ks_part)
{
    const int bh = blockIdx.x;
    const int b  = bh >> 4;
    const int h  = bh & 15;
    const int n0 = blockIdx.y * 512;
    const int t  = threadIdx.x;

    __shared__ __align__(16) float Ks[32][64];
    __shared__ __align__(16) float Vs[32][64];

    float acc[4][4];
    #pragma unroll
    for (int i = 0; i < 4; i++)
        #pragma unroll
        for (int j = 0; j < 4; j++) acc[i][j] = 0.0f;
    float ksacc = 0.0f;

    const int d0 = (t >> 4) * 4;
    const int e0 = (t & 15) * 4;
    const int myd = t & 63;
    const int q4  = t >> 6;

    for (int s0 = 0; s0 < 512; s0 += 32) {
        #pragma unroll
        for (int i = 0; i < 2; i++) {
            int slot = t + 256 * i;
            int r  = slot >> 4;
            int c4 = (slot & 15) * 4;
            size_t base = (size_t)(b * 4096 + n0 + s0 + r) * 3072 + h * 64 + c4;
            *(float4*)&Ks[r][c4] = *(const float4*)(qkv + base + 1024);
            *(float4*)&Vs[r][c4] = *(const float4*)(qkv + base + 2048);
        }
        __syncthreads();

        #pragma unroll 8
        for (int s = 0; s < 32; s++) {
            float kd[4], ve[4];
            #pragma unroll
            for (int i = 0; i < 4; i++) kd[i] = Ks[s][d0 + i];
            #pragma unroll
            for (int i = 0; i < 4; i++) ve[i] = Vs[s][e0 + i];
            #pragma unroll
            for (int i = 0; i < 4; i++)
                #pragma unroll
                for (int j = 0; j < 4; j++) acc[i][j] += kd[i] * ve[j];
        }
        #pragma unroll
        for (int s = q4 * 8; s < q4 * 8 + 8; s++) ksacc += Ks[s][myd];
        __syncthreads();
    }

    float* dst = kv_part + ((size_t)blockIdx.y * 64 + bh) * 4096;
    #pragma unroll
    for (int i = 0; i < 4; i++)
        #pragma unroll
        for (int j = 0; j < 4; j++)
            dst[(d0 + i) * 64 + e0 + j] = acc[i][j];

    ((float*)Ks)[q4 * 64 + myd] = ksacc;
    __syncthreads();
    if (t < 64) {
        float s = ((float*)Ks)[t] + ((float*)Ks)[64 + t] +
                  ((float*)Ks)[128 + t] + ((float*)Ks)[192 + t];
        ks_part[((size_t)blockIdx.y * 64 + bh) * 64 + t] = s;
    }
}

__global__ __launch_bounds__(256) void kv_reduce_kernel(
    const float* __restrict__ kv_part, const float* __restrict__ ks_part,
    float* __restrict__ kv, float* __restrict__ ks)
{
    const int bh = blockIdx.x;
    const int t  = threadIdx.x;
    for (int idx = t; idx < 4096; idx += 256) {
        float s = 0.0f;
        #pragma unroll
        for (int c = 0; c < 8; c++)
            s += kv_part[((size_t)c * 64 + bh) * 4096 + idx];
        kv[(size_t)bh * 4096 + idx] = s;
    }
    if (t < 64) {
        float s = 0.0f;
        #pragma unroll
        for (int c = 0; c < 8; c++)
            s += ks_part[((size_t)c * 64 + bh) * 64 + t];
        ks[bh * 64 + t] = s;
    }
}

// ---------------------------------------------------------------------------
// attn_out v2: thread-per-row, no shuffles.
// Lane owns one row; its q row staged in a lane-private stride-32 smem column
// (conflict-free reads at fixed d). kv rows read as float4 smem broadcasts.
// acc[64] per thread; z fused as 65th accumulator. grid (64 bh, 8), 256 thr.
// ---------------------------------------------------------------------------
__global__ __launch_bounds__(256) void attn_out_kernel(
    const float* __restrict__ qkv, const float* __restrict__ kv,
    const float* __restrict__ ks, float* __restrict__ attn)
{
    extern __shared__ float sm[];
    float* kvs = sm;                 // [64][64]
    float* kss = sm + 4096;          // [64]
    float* qsT = sm + 4096 + 64;     // 8 warps x [64][32]

    const int bh = blockIdx.x;
    const int b  = bh >> 4;
    const int h  = bh & 15;
    const int t  = threadIdx.x;
    const int lane = t & 31;
    const int w    = t >> 5;

    for (int idx = t; idx < 4096; idx += 256)
        kvs[idx] = kv[(size_t)bh * 4096 + idx];
    if (t < 64) kss[t] = ks[bh * 64 + t];
    __syncthreads();

    float* q = qsT + w * 2048;       // this warp's [64][32] region

    #pragma unroll 1
    for (int pass = 0; pass < 2; ++pass) {
        const int n_row = blockIdx.y * 512 + pass * 256 + w * 32 + lane;
        const size_t gbase = (size_t)(b * 4096 + n_row) * 3072 + h * 64;

        // stage own q row transposed: q[d][lane] (stride 32 -> lane-distinct banks)
        #pragma unroll
        for (int c = 0; c < 16; c++) {
            float4 v = *(const float4*)(qkv + gbase + c * 4);
            q[(c * 4 + 0) * 32 + lane] = v.x;
            q[(c * 4 + 1) * 32 + lane] = v.y;
            q[(c * 4 + 2) * 32 + lane] = v.z;
            q[(c * 4 + 3) * 32 + lane] = v.w;
        }

        float acc[64];
        #pragma unroll
        for (int e = 0; e < 64; e++) acc[e] = 0.0f;
        float zacc = 0.0f;

        #pragma unroll 4
        for (int dd = 0; dd < 64; dd++) {
            const float qv = q[dd * 32 + lane];
            zacc += qv * kss[dd];
            const float4* kvr = (const float4*)(kvs + dd * 64);
            #pragma unroll
            for (int e4 = 0; e4 < 16; e4++) {
                float4 kvv = kvr[e4];
                acc[e4 * 4 + 0] += qv * kvv.x;
                acc[e4 * 4 + 1] += qv * kvv.y;
                acc[e4 * 4 + 2] += qv * kvv.z;
                acc[e4 * 4 + 3] += qv * kvv.w;
            }
        }

        const float z = 1.0f / (zacc + 1e-6f);
        float* o = attn + (size_t)(b * 4096 + n_row) * 1024 + h * 64;
        #pragma unroll
        for (int e4 = 0; e4 < 16; e4++)
            *(float4*)(o + e4 * 4) = make_float4(acc[e4*4] * z, acc[e4*4+1] * z,
                                                 acc[e4*4+2] * z, acc[e4*4+3] * z);
    }
}

// ---------------------------------------------------------------------------
extern "C" void kernel_launch(void* const* d_in, const int* in_sizes, int n_in,
                              void* d_out, int out_size)
{
    const float* x    = (const float*)d_in[0];  // [4,4096,1024]
    const float* Wqkv = (const float*)d_in[1];  // [3072,1024]
    const float* Wp   = (const float*)d_in[2];  // [1024,1024]
    const float* bp   = (const float*)d_in[3];  // [1024]
    float* out = (float*)d_out;                 // [4,4096,1024]

    float *qkv, *attn, *kvp, *ksp, *kv, *ks;
    cudaGetSymbolAddress((void**)&qkv,  g_qkv);
    cudaGetSymbolAddress((void**)&attn, g_attn);
    cudaGetSymbolAddress((void**)&kvp,  g_kv_part);
    cudaGetSymbolAddress((void**)&ksp,  g_ks_part);
    cudaGetSymbolAddress((void**)&kv,   g_kv);
    cudaGetSymbolAddress((void**)&ks,   g_ks);

    cudaFuncSetAttribute(gemm_tf32<true, false>,
                         cudaFuncAttributeMaxDynamicSharedMemorySize, SMEM_GEMM);
    cudaFuncSetAttribute(gemm_tf32<false, true>,
                         cudaFuncAttributeMaxDynamicSharedMemorySize, SMEM_GEMM);
    cudaFuncSetAttribute(attn_out_kernel,
                         cudaFuncAttributeMaxDynamicSharedMemorySize, AO_SMEM);

    // 1) qkv = x @ W_qkv^T, phi fused on q,k (cols < 2048)
    gemm_tf32<true, false><<<dim3(24, 64), 256, SMEM_GEMM>>>(
        x, Wqkv, nullptr, qkv, 16384, 3072, 1024);
    // 2) kv outer-product + k_sum partials, then reduce
    kv_partial_kernel<<<dim3(64, 8), 256>>>(qkv, kvp, ksp);
    kv_reduce_kernel<<<64, 256>>>(kvp, ksp, kv, ks);
    // 3) normalize + q @ kv -> attn
    attn_out_kernel<<<dim3(64, 8), 256, AO_SMEM>>>(qkv, kv, ks, attn);
    // 4) out = attn @ W_proj^T + b_proj
    gemm_tf32<false, true><<<dim3(8, 64), 256, SMEM_GEMM>>>(
        attn, Wp, bp, out, 16384, 1024, 1024);
}

// round 15
// speedup vs baseline: 1.8834x; 1.8834x over previous
#include <cuda_runtime.h>
#include <cuda_fp16.h>
#include <cstdint>
#include <math.h>

// Problem constants: B=4, N=4096, C=1024, h=16, d=64 ; M = 16384, K = 1024
#define BM 128
#define BN 128
#define BKH 32                        // K-tile in halves (64B per row chunk)
#define STAGES 3
#define LDAH 40                       // BKH + 8 pad halves; 80B row stride
#define SMEM_GEMM (STAGES * (BM + BN) * LDAH * 2)

// Scratch (static __device__ globals; no allocations allowed)
__device__ float g_qkv[50331648];    // [16384, 3072] fp32 (phi applied to q,k)
__device__ float g_kv_part[2097152]; // [8][64][64][64]
__device__ float g_ks_part[32768];   // [8][64][64]
__device__ float g_kv[262144];       // [64][64][64]
__device__ float g_ks[4096];         // [64][64]
__device__ __align__(16) __half g_xh[16777216];    // x in fp16
__device__ __align__(16) __half g_wqkvh[3145728];  // W_qkv in fp16
__device__ __align__(16) __half g_wph[1048576];    // W_proj in fp16
__device__ __align__(16) __half g_attnh[16777216]; // attn out in fp16

// ---------------------------------------------------------------------------
// PTX helpers (sm_80-baseline ISA only; target is plain sm_100)
// ---------------------------------------------------------------------------
static __device__ __forceinline__ void cp_async16(__half* s, const __half* g) {
    unsigned int sa = (unsigned int)__cvta_generic_to_shared(s);
    asm volatile("cp.async.cg.shared.global [%0], [%1], 16;\n" :: "r"(sa), "l"(g));
}
#define CP_COMMIT() asm volatile("cp.async.commit_group;\n" ::)
#define CP_WAIT(n)  asm volatile("cp.async.wait_group %0;\n" :: "n"(n))

static __device__ __forceinline__ void ldsm4h(uint32_t r[4], const __half* p) {
    unsigned int sa = (unsigned int)__cvta_generic_to_shared(p);
    asm volatile("ldmatrix.sync.aligned.m8n8.x4.shared.b16 {%0,%1,%2,%3}, [%4];"
                 : "=r"(r[0]), "=r"(r[1]), "=r"(r[2]), "=r"(r[3]) : "r"(sa));
}
static __device__ __forceinline__ void mma16n8k16(
    float d[4], const uint32_t a[4], uint32_t b0, uint32_t b1)
{
    asm volatile(
        "mma.sync.aligned.m16n8k16.row.col.f32.f16.f16.f32 "
        "{%0,%1,%2,%3}, {%4,%5,%6,%7}, {%8,%9}, {%0,%1,%2,%3};"
        : "+f"(d[0]), "+f"(d[1]), "+f"(d[2]), "+f"(d[3])
        : "r"(a[0]), "r"(a[1]), "r"(a[2]), "r"(a[3]), "r"(b0), "r"(b1));
}

// ---------------------------------------------------------------------------
// fp32 -> fp16 conversion (grid-stride, 4 elems/thread)
// ---------------------------------------------------------------------------
__global__ __launch_bounds__(256) void f2h_kernel(
    const float4* __restrict__ in, __half2* __restrict__ out, int n4)
{
    int i = blockIdx.x * 256 + threadIdx.x;
    if (i < n4) {
        float4 v = in[i];
        out[2 * i]     = __floats2half2_rn(v.x, v.y);
        out[2 * i + 1] = __floats2half2_rn(v.z, v.w);
    }
}

// ---------------------------------------------------------------------------
// FP16 mma.sync GEMM, 3-stage cp.async pipeline, native b16 ldmatrix.
// C[m,n] = sum_k A[m,k]*W[n,k] (+bias[n]) (+phi if n0<2048). fp32 accum/out.
// 128x128 CTA tile, 256 threads (8 warps: 4M x 2N), warp tile 32x64.
// ---------------------------------------------------------------------------
template <bool DO_PHI, bool DO_BIAS>
__global__ __launch_bounds__(256, 2) void gemm_f16(
    const __half* __restrict__ A, const __half* __restrict__ W,
    const float* __restrict__ bias, float* __restrict__ C,
    int M, int N, int K)
{
    extern __shared__ __half smem[];
    __half* As = smem;                        // [STAGES][BM*LDAH]
    __half* Bs = smem + STAGES * BM * LDAH;   // [STAGES][BN*LDAH]
    __shared__ float bias_sm[BN];

    const int t  = threadIdx.x;
    const int n0 = blockIdx.x * BN;
    const int m0 = blockIdx.y * BM;
    const int warp = t >> 5;
    const int lane = t & 31;
    const int wm = warp & 3;       // 32 rows each
    const int wn = warp >> 2;      // 64 cols each

    const __half* Ablk = A + (size_t)m0 * K;
    const __half* Wblk = W + (size_t)n0 * K;

    if (DO_BIAS && t < BN) bias_sm[t] = bias[n0 + t];

    // cp.async: 128x32h tile = 128 rows x 4 chunks of 16B = 512 slots, 2/thread
    int rr[2], cc[2];
    #pragma unroll
    for (int i = 0; i < 2; i++) {
        int slot = t + 256 * i;
        rr[i] = slot >> 2;
        cc[i] = (slot & 3) * 8;    // halves offset (16B chunks)
    }

    auto stage_load = [&](int kt, int s) {
        const int k0 = kt * BKH;
        __half* as = As + s * BM * LDAH;
        __half* bs = Bs + s * BN * LDAH;
        #pragma unroll
        for (int i = 0; i < 2; i++) {
            cp_async16(as + rr[i] * LDAH + cc[i], Ablk + (size_t)rr[i] * K + k0 + cc[i]);
            cp_async16(bs + rr[i] * LDAH + cc[i], Wblk + (size_t)rr[i] * K + k0 + cc[i]);
        }
    };

    const int nk = K / BKH;
    #pragma unroll
    for (int s = 0; s < STAGES - 1; s++) {
        stage_load(s, s);
        CP_COMMIT();
    }

    float d[2][8][4];
    #pragma unroll
    for (int i = 0; i < 2; i++)
        #pragma unroll
        for (int j = 0; j < 8; j++)
            #pragma unroll
            for (int e = 0; e < 4; e++) d[i][j][e] = 0.0f;

    // ldmatrix lane addressing (canonical m16n8k16 recipes):
    //  A (m16k16, row-major): row = base + (lane&15), colh = kk + (lane>>4)*8
    //  B (n16k16, [n][k] rows): row = base + (lane&7) + (lane>>4)*8,
    //                           colh = kk + ((lane>>3)&1)*8
    const int a_r = lane & 15;
    const int a_c = (lane >> 4) * 8;
    const int b_r = (lane & 7) + ((lane >> 4) * 8);
    const int b_c = ((lane >> 3) & 1) * 8;

    for (int kt = 0; kt < nk; ++kt) {
        CP_WAIT(STAGES - 2);
        __syncthreads();

        const int nxt = kt + STAGES - 1;
        if (nxt < nk) stage_load(nxt, nxt % STAGES);
        CP_COMMIT();

        const __half* as = As + (kt % STAGES) * BM * LDAH;
        const __half* bs = Bs + (kt % STAGES) * BN * LDAH;

        #pragma unroll
        for (int kk = 0; kk < BKH; kk += 16) {
            uint32_t a[2][4], b[4][4];
            #pragma unroll
            for (int i = 0; i < 2; i++)
                ldsm4h(a[i], as + (wm * 32 + i * 16 + a_r) * LDAH + kk + a_c);
            #pragma unroll
            for (int j = 0; j < 4; j++)
                ldsm4h(b[j], bs + (wn * 64 + j * 16 + b_r) * LDAH + kk + b_c);
            #pragma unroll
            for (int i = 0; i < 2; i++)
                #pragma unroll
                for (int jj = 0; jj < 8; jj++)
                    mma16n8k16(d[i][jj], a[i],
                               b[jj >> 1][(jj & 1) * 2], b[jj >> 1][(jj & 1) * 2 + 1]);
        }
        __syncthreads();
    }

    // ---- epilogue: direct register->global fp32 stores ----
    const bool phi = DO_PHI && (n0 < 2048);
    const int er = lane >> 2;            // row within frag (0..7)
    const int ec = (lane & 3) * 2;       // col within n8 (0,2,4,6)
    #pragma unroll
    for (int i = 0; i < 2; i++) {
        const int grow = m0 + wm * 32 + i * 16 + er;
        #pragma unroll
        for (int jj = 0; jj < 8; jj++) {
            const int lcol = wn * 64 + jj * 8 + ec;
            float v[4];
            #pragma unroll
            for (int e = 0; e < 4; e++) v[e] = d[i][jj][e];
            if (phi) {
                #pragma unroll
                for (int e = 0; e < 4; e++) v[e] = expf(-0.5f * v[e] * v[e]);
            }
            if (DO_BIAS) {
                v[0] += bias_sm[lcol];     v[1] += bias_sm[lcol + 1];
                v[2] += bias_sm[lcol];     v[3] += bias_sm[lcol + 1];
            }
            *(float2*)(C + (size_t)grow * N + n0 + lcol) = make_float2(v[0], v[1]);
            *(float2*)(C + (size_t)(grow + 8) * N + n0 + lcol) = make_float2(v[2], v[3]);
        }
    }
}

// ---------------------------------------------------------------------------
// kv partials: kv[b,h,d,e] = sum_n phiK * V  (8 sequence chunks) + k_sum.
// ---------------------------------------------------------------------------
__global__ __launch_bounds__(256) void kv_partial_kernel(
    const float* __restrict__ qkv, float* __restrict__ kv_part,
    float* __restrict__ ks_part)
{
    const int bh = blockIdx.x;
    const int b  = bh >> 4;
    const int h  = bh & 15;
    const int n0 = blockIdx.y * 512;
    const int t  = threadIdx.x;

    __shared__ __align__(16) float Ks[32][64];
    __shared__ __align__(16) float Vs[32][64];

    float acc[4][4];
    #pragma unroll
    for (int i = 0; i < 4; i++)
        #pragma unroll
        for (int j = 0; j < 4; j++) acc[i][j] = 0.0f;
    float ksacc = 0.0f;

    const int d0 = (t >> 4) * 4;
    const int e0 = (t & 15) * 4;
    const int myd = t & 63;
    const int q4  = t >> 6;

    for (int s0 = 0; s0 < 512; s0 += 32) {
        #pragma unroll
        for (int i = 0; i < 2; i++) {
            int slot = t + 256 * i;
            int r  = slot >> 4;
            int c4 = (slot & 15) * 4;
            size_t base = (size_t)(b * 4096 + n0 + s0 + r) * 3072 + h * 64 + c4;
            *(float4*)&Ks[r][c4] = *(const float4*)(qkv + base + 1024);
            *(float4*)&Vs[r][c4] = *(const float4*)(qkv + base + 2048);
        }
        __syncthreads();

        #pragma unroll 8
        for (int s = 0; s < 32; s++) {
            float kd[4], ve[4];
            #pragma unroll
            for (int i = 0; i < 4; i++) kd[i] = Ks[s][d0 + i];
            #pragma unroll
            for (int i = 0; i < 4; i++) ve[i] = Vs[s][e0 + i];
            #pragma unroll
            for (int i = 0; i < 4; i++)
                #pragma unroll
                for (int j = 0; j < 4; j++) acc[i][j] += kd[i] * ve[j];
        }
        #pragma unroll
        for (int s = q4 * 8; s < q4 * 8 + 8; s++) ksacc += Ks[s][myd];
        __syncthreads();
    }

    float* dst = kv_part + ((size_t)blockIdx.y * 64 + bh) * 4096;
    #pragma unroll
    for (int i = 0; i < 4; i++)
        #pragma unroll
        for (int j = 0; j < 4; j++)
            dst[(d0 + i) * 64 + e0 + j] = acc[i][j];

    ((float*)Ks)[q4 * 64 + myd] = ksacc;
    __syncthreads();
    if (t < 64) {
        float s = ((float*)Ks)[t] + ((float*)Ks)[64 + t] +
                  ((float*)Ks)[128 + t] + ((float*)Ks)[192 + t];
        ks_part[((size_t)blockIdx.y * 64 + bh) * 64 + t] = s;
    }
}

__global__ __launch_bounds__(256) void kv_reduce_kernel(
    const float* __restrict__ kv_part, const float* __restrict__ ks_part,
    float* __restrict__ kv, float* __restrict__ ks)
{
    const int bh = blockIdx.x;
    const int t  = threadIdx.x;
    for (int idx = t; idx < 4096; idx += 256) {
        float s = 0.0f;
        #pragma unroll
        for (int c = 0; c < 8; c++)
            s += kv_part[((size_t)c * 64 + bh) * 4096 + idx];
        kv[(size_t)bh * 4096 + idx] = s;
    }
    if (t < 64) {
        float s = 0.0f;
        #pragma unroll
        for (int c = 0; c < 8; c++)
            s += ks_part[((size_t)c * 64 + bh) * 64 + t];
        ks[bh * 64 + t] = s;
    }
}

// ---------------------------------------------------------------------------
// attn_out (R9-proven version): 8 rows per warp register-blocked via shuffle;
// kv tile in smem. Output written as fp16 for the fp16 proj GEMM.
// grid (64 bh, 8 chunks), 256 threads.
// ---------------------------------------------------------------------------
__global__ __launch_bounds__(256) void attn_out_kernel(
    const float* __restrict__ qkv, const float* __restrict__ kv,
    const float* __restrict__ ks, __half* __restrict__ attn)
{
    const int bh = blockIdx.x;
    const int b  = bh >> 4;
    const int h  = bh & 15;
    const int t  = threadIdx.x;
    const int lane = t & 31;
    const int w    = t >> 5;

    __shared__ float kvs[64][65];
    __shared__ float kss[64];

    for (int idx = t; idx < 4096; idx += 256)
        kvs[idx >> 6][idx & 63] = kv[(size_t)bh * 4096 + idx];
    if (t < 64) kss[t] = ks[bh * 64 + t];
    __syncthreads();

    const int nbase = blockIdx.y * 512 + w * 64;
    for (int g = 0; g < 8; ++g) {
        const int n = nbase + g * 8;
        float q0[8], q1[8], a0[8], a1[8], z[8];
        #pragma unroll
        for (int r = 0; r < 8; r++) {
            size_t base = (size_t)(b * 4096 + n + r) * 3072 + h * 64;
            q0[r] = qkv[base + lane];
            q1[r] = qkv[base + 32 + lane];
            a0[r] = 0.0f; a1[r] = 0.0f;
        }
        #pragma unroll
        for (int r = 0; r < 8; r++) {
            float zp = q0[r] * kss[lane] + q1[r] * kss[32 + lane];
            #pragma unroll
            for (int o = 16; o; o >>= 1) zp += __shfl_xor_sync(0xFFFFFFFFu, zp, o);
            z[r] = 1.0f / (zp + 1e-6f);
        }

        #pragma unroll 4
        for (int d = 0; d < 32; d++) {
            float kv0 = kvs[d][lane];
            float kv1 = kvs[d][32 + lane];
            #pragma unroll
            for (int r = 0; r < 8; r++) {
                float qd = __shfl_sync(0xFFFFFFFFu, q0[r], d);
                a0[r] += qd * kv0;
                a1[r] += qd * kv1;
            }
        }
        #pragma unroll 4
        for (int d = 0; d < 32; d++) {
            float kv0 = kvs[32 + d][lane];
            float kv1 = kvs[32 + d][32 + lane];
            #pragma unroll
            for (int r = 0; r < 8; r++) {
                float qd = __shfl_sync(0xFFFFFFFFu, q1[r], d);
                a0[r] += qd * kv0;
                a1[r] += qd * kv1;
            }
        }

        #pragma unroll
        for (int r = 0; r < 8; r++) {
            __half* o = attn + (size_t)(b * 4096 + n + r) * 1024 + h * 64;
            o[lane]      = __float2half_rn(a0[r] * z[r]);
            o[lane + 32] = __float2half_rn(a1[r] * z[r]);
        }
    }
}

// ---------------------------------------------------------------------------
extern "C" void kernel_launch(void* const* d_in, const int* in_sizes, int n_in,
                              void* d_out, int out_size)
{
    const float* x    = (const float*)d_in[0];  // [4,4096,1024]
    const float* Wqkv = (const float*)d_in[1];  // [3072,1024]
    const float* Wp   = (const float*)d_in[2];  // [1024,1024]
    const float* bp   = (const float*)d_in[3];  // [1024]
    float* out = (float*)d_out;                 // [4,4096,1024]

    float *qkv, *kvp, *ksp, *kv, *ks;
    __half *xh, *wqkvh, *wph, *attnh;
    cudaGetSymbolAddress((void**)&qkv,   g_qkv);
    cudaGetSymbolAddress((void**)&kvp,   g_kv_part);
    cudaGetSymbolAddress((void**)&ksp,   g_ks_part);
    cudaGetSymbolAddress((void**)&kv,    g_kv);
    cudaGetSymbolAddress((void**)&ks,    g_ks);
    cudaGetSymbolAddress((void**)&xh,    g_xh);
    cudaGetSymbolAddress((void**)&wqkvh, g_wqkvh);
    cudaGetSymbolAddress((void**)&wph,   g_wph);
    cudaGetSymbolAddress((void**)&attnh, g_attnh);

    cudaFuncSetAttribute(gemm_f16<true, false>,
                         cudaFuncAttributeMaxDynamicSharedMemorySize, SMEM_GEMM);
    cudaFuncSetAttribute(gemm_f16<false, true>,
                         cudaFuncAttributeMaxDynamicSharedMemorySize, SMEM_GEMM);

    // 0) fp32 -> fp16 conversions (inputs only; attn is produced in fp16)
    f2h_kernel<<<16384, 256>>>((const float4*)x,    (__half2*)xh,    4194304);
    f2h_kernel<<<3072,  256>>>((const float4*)Wqkv, (__half2*)wqkvh, 786432);
    f2h_kernel<<<1024,  256>>>((const float4*)Wp,   (__half2*)wph,   262144);

    // 1) qkv = x @ W_qkv^T, phi fused on q,k (cols < 2048)
    gemm_f16<true, false><<<dim3(24, 128), 256, SMEM_GEMM>>>(
        xh, wqkvh, nullptr, qkv, 16384, 3072, 1024);
    // 2) kv outer-product + k_sum partials, then reduce
    kv_partial_kernel<<<dim3(64, 8), 256>>>(qkv, kvp, ksp);
    kv_reduce_kernel<<<64, 256>>>(kvp, ksp, kv, ks);
    // 3) normalize + q @ kv -> attn (fp16)
    attn_out_kernel<<<dim3(64, 8), 256>>>(qkv, kv, ks, attnh);
    // 4) out = attn @ W_proj^T + b_proj
    gemm_f16<false, true><<<dim3(8, 128), 256, SMEM_GEMM>>>(
        attnh, wph, bp, out, 16384, 1024, 1024);
}

// round 16
// speedup vs baseline: 1.9558x; 1.0384x over previous
#include <cuda_runtime.h>
#include <cuda_fp16.h>
#include <cstdint>
#include <math.h>

// Problem constants: B=4, N=4096, C=1024, h=16, d=64 ; M = 16384, K = 1024
#define BM 128
#define BN 128
#define BKH 32                        // K-tile in halves (64B per row chunk)
#define STAGES 4
#define LDAH 40                       // BKH + 8 pad halves; 80B row stride
#define SMEM_GEMM (STAGES * (BM + BN) * LDAH * 2)

// Scratch (static __device__ globals; no allocations allowed)
__device__ float g_kv_part[2097152]; // [8][64][64][64]
__device__ float g_ks_part[32768];   // [8][64][64]
__device__ float g_kv[262144];       // [64][64][64]
__device__ float g_ks[4096];         // [64][64]
__device__ __align__(16) __half g_qkvh[50331648];  // qkv fp16 (phi on q,k)
__device__ __align__(16) __half g_xh[16777216];    // x in fp16
__device__ __align__(16) __half g_wqkvh[3145728];  // W_qkv in fp16
__device__ __align__(16) __half g_wph[1048576];    // W_proj in fp16
__device__ __align__(16) __half g_attnh[16777216]; // attn out in fp16

// ---------------------------------------------------------------------------
// PTX helpers (sm_80-baseline ISA only; target is plain sm_100)
// ---------------------------------------------------------------------------
static __device__ __forceinline__ void cp_async16(__half* s, const __half* g) {
    unsigned int sa = (unsigned int)__cvta_generic_to_shared(s);
    asm volatile("cp.async.cg.shared.global [%0], [%1], 16;\n" :: "r"(sa), "l"(g));
}
#define CP_COMMIT() asm volatile("cp.async.commit_group;\n" ::)
#define CP_WAIT(n)  asm volatile("cp.async.wait_group %0;\n" :: "n"(n))

static __device__ __forceinline__ void ldsm4h(uint32_t r[4], const __half* p) {
    unsigned int sa = (unsigned int)__cvta_generic_to_shared(p);
    asm volatile("ldmatrix.sync.aligned.m8n8.x4.shared.b16 {%0,%1,%2,%3}, [%4];"
                 : "=r"(r[0]), "=r"(r[1]), "=r"(r[2]), "=r"(r[3]) : "r"(sa));
}
static __device__ __forceinline__ void mma16n8k16(
    float d[4], const uint32_t a[4], uint32_t b0, uint32_t b1)
{
    asm volatile(
        "mma.sync.aligned.m16n8k16.row.col.f32.f16.f16.f32 "
        "{%0,%1,%2,%3}, {%4,%5,%6,%7}, {%8,%9}, {%0,%1,%2,%3};"
        : "+f"(d[0]), "+f"(d[1]), "+f"(d[2]), "+f"(d[3])
        : "r"(a[0]), "r"(a[1]), "r"(a[2]), "r"(a[3]), "r"(b0), "r"(b1));
}

// ---------------------------------------------------------------------------
// fp32 -> fp16 conversion (4 elems/thread)
// ---------------------------------------------------------------------------
__global__ __launch_bounds__(256) void f2h_kernel(
    const float4* __restrict__ in, __half2* __restrict__ out, int n4)
{
    int i = blockIdx.x * 256 + threadIdx.x;
    if (i < n4) {
        float4 v = in[i];
        out[2 * i]     = __floats2half2_rn(v.x, v.y);
        out[2 * i + 1] = __floats2half2_rn(v.z, v.w);
    }
}

// ---------------------------------------------------------------------------
// FP16 mma.sync GEMM, 4-stage cp.async pipeline, native b16 ldmatrix.
// C[m,n] = sum_k A[m,k]*W[n,k] (+bias[n]) (+phi if n0<2048). fp32 accum.
// Output fp16 (HALF_OUT) or fp32. 128x128 tile, 256 thr, warp tile 32x64.
// ---------------------------------------------------------------------------
template <bool DO_PHI, bool DO_BIAS, bool HALF_OUT>
__global__ __launch_bounds__(256, 2) void gemm_f16(
    const __half* __restrict__ A, const __half* __restrict__ W,
    const float* __restrict__ bias, float* __restrict__ C,
    __half* __restrict__ Ch, int M, int N, int K)
{
    extern __shared__ __half smem[];
    __half* As = smem;                        // [STAGES][BM*LDAH]
    __half* Bs = smem + STAGES * BM * LDAH;   // [STAGES][BN*LDAH]
    __shared__ float bias_sm[BN];

    const int t  = threadIdx.x;
    const int n0 = blockIdx.x * BN;
    const int m0 = blockIdx.y * BM;
    const int warp = t >> 5;
    const int lane = t & 31;
    const int wm = warp & 3;       // 32 rows each
    const int wn = warp >> 2;      // 64 cols each

    const __half* Ablk = A + (size_t)m0 * K;
    const __half* Wblk = W + (size_t)n0 * K;

    if (DO_BIAS && t < BN) bias_sm[t] = bias[n0 + t];

    // cp.async: 128x32h tile = 512 16B-slots, 2/thread
    int rr[2], cc[2];
    #pragma unroll
    for (int i = 0; i < 2; i++) {
        int slot = t + 256 * i;
        rr[i] = slot >> 2;
        cc[i] = (slot & 3) * 8;    // halves offset
    }

    auto stage_load = [&](int kt, int s) {
        const int k0 = kt * BKH;
        __half* as = As + s * BM * LDAH;
        __half* bs = Bs + s * BN * LDAH;
        #pragma unroll
        for (int i = 0; i < 2; i++) {
            cp_async16(as + rr[i] * LDAH + cc[i], Ablk + (size_t)rr[i] * K + k0 + cc[i]);
            cp_async16(bs + rr[i] * LDAH + cc[i], Wblk + (size_t)rr[i] * K + k0 + cc[i]);
        }
    };

    const int nk = K / BKH;
    #pragma unroll
    for (int s = 0; s < STAGES - 1; s++) {
        stage_load(s, s);
        CP_COMMIT();
    }

    float d[2][8][4];
    #pragma unroll
    for (int i = 0; i < 2; i++)
        #pragma unroll
        for (int j = 0; j < 8; j++)
            #pragma unroll
            for (int e = 0; e < 4; e++) d[i][j][e] = 0.0f;

    //  A (m16k16 row-major): row = base + (lane&15), colh = kk + (lane>>4)*8
    //  B (n16k16 [n][k]):    row = base + (lane&7) + (lane>>4)*8,
    //                        colh = kk + ((lane>>3)&1)*8
    const int a_r = lane & 15;
    const int a_c = (lane >> 4) * 8;
    const int b_r = (lane & 7) + ((lane >> 4) * 8);
    const int b_c = ((lane >> 3) & 1) * 8;

    for (int kt = 0; kt < nk; ++kt) {
        CP_WAIT(STAGES - 2);
        __syncthreads();

        const int nxt = kt + STAGES - 1;
        if (nxt < nk) stage_load(nxt, nxt % STAGES);
        CP_COMMIT();

        const __half* as = As + (kt % STAGES) * BM * LDAH;
        const __half* bs = Bs + (kt % STAGES) * BN * LDAH;

        #pragma unroll
        for (int kk = 0; kk < BKH; kk += 16) {
            uint32_t a[2][4], b[4][4];
            #pragma unroll
            for (int i = 0; i < 2; i++)
                ldsm4h(a[i], as + (wm * 32 + i * 16 + a_r) * LDAH + kk + a_c);
            #pragma unroll
            for (int j = 0; j < 4; j++)
                ldsm4h(b[j], bs + (wn * 64 + j * 16 + b_r) * LDAH + kk + b_c);
            #pragma unroll
            for (int i = 0; i < 2; i++)
                #pragma unroll
                for (int jj = 0; jj < 8; jj++)
                    mma16n8k16(d[i][jj], a[i],
                               b[jj >> 1][(jj & 1) * 2], b[jj >> 1][(jj & 1) * 2 + 1]);
        }
        __syncthreads();
    }

    // ---- epilogue ----
    const bool phi = DO_PHI && (n0 < 2048);
    const int er = lane >> 2;
    const int ec = (lane & 3) * 2;
    #pragma unroll
    for (int i = 0; i < 2; i++) {
        const int grow = m0 + wm * 32 + i * 16 + er;
        #pragma unroll
        for (int jj = 0; jj < 8; jj++) {
            const int lcol = wn * 64 + jj * 8 + ec;
            float v[4];
            #pragma unroll
            for (int e = 0; e < 4; e++) v[e] = d[i][jj][e];
            if (phi) {
                #pragma unroll
                for (int e = 0; e < 4; e++) v[e] = expf(-0.5f * v[e] * v[e]);
            }
            if (DO_BIAS) {
                v[0] += bias_sm[lcol];     v[1] += bias_sm[lcol + 1];
                v[2] += bias_sm[lcol];     v[3] += bias_sm[lcol + 1];
            }
            if (HALF_OUT) {
                *(__half2*)(Ch + (size_t)grow * N + n0 + lcol) =
                    __floats2half2_rn(v[0], v[1]);
                *(__half2*)(Ch + (size_t)(grow + 8) * N + n0 + lcol) =
                    __floats2half2_rn(v[2], v[3]);
            } else {
                *(float2*)(C + (size_t)grow * N + n0 + lcol) = make_float2(v[0], v[1]);
                *(float2*)(C + (size_t)(grow + 8) * N + n0 + lcol) = make_float2(v[2], v[3]);
            }
        }
    }
}

// ---------------------------------------------------------------------------
// kv partials from fp16 qkv: kv[b,h,d,e] = sum_n phiK * V (+ k_sum partials).
// ---------------------------------------------------------------------------
__global__ __launch_bounds__(256) void kv_partial_kernel(
    const __half* __restrict__ qkv, float* __restrict__ kv_part,
    float* __restrict__ ks_part)
{
    const int bh = blockIdx.x;
    const int b  = bh >> 4;
    const int h  = bh & 15;
    const int n0 = blockIdx.y * 512;
    const int t  = threadIdx.x;

    __shared__ __align__(16) float Ks[32][64];
    __shared__ __align__(16) float Vs[32][64];

    float acc[4][4];
    #pragma unroll
    for (int i = 0; i < 4; i++)
        #pragma unroll
        for (int j = 0; j < 4; j++) acc[i][j] = 0.0f;
    float ksacc = 0.0f;

    const int d0 = (t >> 4) * 4;
    const int e0 = (t & 15) * 4;
    const int myd = t & 63;
    const int q4  = t >> 6;

    // loader mapping: 256 slots of 8 halves per 32x64 tile
    const int lrow = t >> 3;
    const int lc8  = (t & 7) * 8;

    for (int s0 = 0; s0 < 512; s0 += 32) {
        {
            size_t base = (size_t)(b * 4096 + n0 + s0 + lrow) * 3072 + h * 64 + lc8;
            const __half2* kp = (const __half2*)(qkv + base + 1024);
            const __half2* vp = (const __half2*)(qkv + base + 2048);
            #pragma unroll
            for (int i = 0; i < 4; i++) {
                float2 kf = __half22float2(kp[i]);
                float2 vf = __half22float2(vp[i]);
                Ks[lrow][lc8 + 2 * i]     = kf.x;
                Ks[lrow][lc8 + 2 * i + 1] = kf.y;
                Vs[lrow][lc8 + 2 * i]     = vf.x;
                Vs[lrow][lc8 + 2 * i + 1] = vf.y;
            }
        }
        __syncthreads();

        #pragma unroll 8
        for (int s = 0; s < 32; s++) {
            float kd[4], ve[4];
            #pragma unroll
            for (int i = 0; i < 4; i++) kd[i] = Ks[s][d0 + i];
            #pragma unroll
            for (int i = 0; i < 4; i++) ve[i] = Vs[s][e0 + i];
            #pragma unroll
            for (int i = 0; i < 4; i++)
                #pragma unroll
                for (int j = 0; j < 4; j++) acc[i][j] += kd[i] * ve[j];
        }
        #pragma unroll
        for (int s = q4 * 8; s < q4 * 8 + 8; s++) ksacc += Ks[s][myd];
        __syncthreads();
    }

    float* dst = kv_part + ((size_t)blockIdx.y * 64 + bh) * 4096;
    #pragma unroll
    for (int i = 0; i < 4; i++)
        #pragma unroll
        for (int j = 0; j < 4; j++)
            dst[(d0 + i) * 64 + e0 + j] = acc[i][j];

    ((float*)Ks)[q4 * 64 + myd] = ksacc;
    __syncthreads();
    if (t < 64) {
        float s = ((float*)Ks)[t] + ((float*)Ks)[64 + t] +
                  ((float*)Ks)[128 + t] + ((float*)Ks)[192 + t];
        ks_part[((size_t)blockIdx.y * 64 + bh) * 64 + t] = s;
    }
}

__global__ __launch_bounds__(256) void kv_reduce_kernel(
    const float* __restrict__ kv_part, const float* __restrict__ ks_part,
    float* __restrict__ kv, float* __restrict__ ks)
{
    const int bh = blockIdx.x;
    const int t  = threadIdx.x;
    for (int idx = t; idx < 4096; idx += 256) {
        float s = 0.0f;
        #pragma unroll
        for (int c = 0; c < 8; c++)
            s += kv_part[((size_t)c * 64 + bh) * 4096 + idx];
        kv[(size_t)bh * 4096 + idx] = s;
    }
    if (t < 64) {
        float s = 0.0f;
        #pragma unroll
        for (int c = 0; c < 8; c++)
            s += ks_part[((size_t)c * 64 + bh) * 64 + t];
        ks[bh * 64 + t] = s;
    }
}

// ---------------------------------------------------------------------------
// attn_out: 8 rows/warp register-blocked via shuffle; q read as fp16;
// kv tile fp32 in smem; output fp16. grid (64 bh, 8), 256 threads.
// ---------------------------------------------------------------------------
__global__ __launch_bounds__(256) void attn_out_kernel(
    const __half* __restrict__ qkv, const float* __restrict__ kv,
    const float* __restrict__ ks, __half* __restrict__ attn)
{
    const int bh = blockIdx.x;
    const int b  = bh >> 4;
    const int h  = bh & 15;
    const int t  = threadIdx.x;
    const int lane = t & 31;
    const int w    = t >> 5;

    __shared__ float kvs[64][65];
    __shared__ float kss[64];

    for (int idx = t; idx < 4096; idx += 256)
        kvs[idx >> 6][idx & 63] = kv[(size_t)bh * 4096 + idx];
    if (t < 64) kss[t] = ks[bh * 64 + t];
    __syncthreads();

    const int nbase = blockIdx.y * 512 + w * 64;
    for (int g = 0; g < 8; ++g) {
        const int n = nbase + g * 8;
        float q0[8], q1[8], a0[8], a1[8], z[8];
        #pragma unroll
        for (int r = 0; r < 8; r++) {
            size_t base = (size_t)(b * 4096 + n + r) * 3072 + h * 64;
            q0[r] = __half2float(qkv[base + lane]);
            q1[r] = __half2float(qkv[base + 32 + lane]);
            a0[r] = 0.0f; a1[r] = 0.0f;
        }
        #pragma unroll
        for (int r = 0; r < 8; r++) {
            float zp = q0[r] * kss[lane] + q1[r] * kss[32 + lane];
            #pragma unroll
            for (int o = 16; o; o >>= 1) zp += __shfl_xor_sync(0xFFFFFFFFu, zp, o);
            z[r] = 1.0f / (zp + 1e-6f);
        }

        #pragma unroll 4
        for (int d = 0; d < 32; d++) {
            float kv0 = kvs[d][lane];
            float kv1 = kvs[d][32 + lane];
            #pragma unroll
            for (int r = 0; r < 8; r++) {
                float qd = __shfl_sync(0xFFFFFFFFu, q0[r], d);
                a0[r] += qd * kv0;
                a1[r] += qd * kv1;
            }
        }
        #pragma unroll 4
        for (int d = 0; d < 32; d++) {
            float kv0 = kvs[32 + d][lane];
            float kv1 = kvs[32 + d][32 + lane];
            #pragma unroll
            for (int r = 0; r < 8; r++) {
                float qd = __shfl_sync(0xFFFFFFFFu, q1[r], d);
                a0[r] += qd * kv0;
                a1[r] += qd * kv1;
            }
        }

        #pragma unroll
        for (int r = 0; r < 8; r++) {
            __half* o = attn + (size_t)(b * 4096 + n + r) * 1024 + h * 64;
            o[lane]      = __float2half_rn(a0[r] * z[r]);
            o[lane + 32] = __float2half_rn(a1[r] * z[r]);
        }
    }
}

// ---------------------------------------------------------------------------
extern "C" void kernel_launch(void* const* d_in, const int* in_sizes, int n_in,
                              void* d_out, int out_size)
{
    const float* x    = (const float*)d_in[0];  // [4,4096,1024]
    const float* Wqkv = (const float*)d_in[1];  // [3072,1024]
    const float* Wp   = (const float*)d_in[2];  // [1024,1024]
    const float* bp   = (const float*)d_in[3];  // [1024]
    float* out = (float*)d_out;                 // [4,4096,1024]

    float *kvp, *ksp, *kv, *ks;
    __half *qkvh, *xh, *wqkvh, *wph, *attnh;
    cudaGetSymbolAddress((void**)&kvp,   g_kv_part);
    cudaGetSymbolAddress((void**)&ksp,   g_ks_part);
    cudaGetSymbolAddress((void**)&kv,    g_kv);
    cudaGetSymbolAddress((void**)&ks,    g_ks);
    cudaGetSymbolAddress((void**)&qkvh,  g_qkvh);
    cudaGetSymbolAddress((void**)&xh,    g_xh);
    cudaGetSymbolAddress((void**)&wqkvh, g_wqkvh);
    cudaGetSymbolAddress((void**)&wph,   g_wph);
    cudaGetSymbolAddress((void**)&attnh, g_attnh);

    cudaFuncSetAttribute(gemm_f16<true, false, true>,
                         cudaFuncAttributeMaxDynamicSharedMemorySize, SMEM_GEMM);
    cudaFuncSetAttribute(gemm_f16<false, true, false>,
                         cudaFuncAttributeMaxDynamicSharedMemorySize, SMEM_GEMM);

    // 0) fp32 -> fp16 conversions
    f2h_kernel<<<16384, 256>>>((const float4*)x,    (__half2*)xh,    4194304);
    f2h_kernel<<<3072,  256>>>((const float4*)Wqkv, (__half2*)wqkvh, 786432);
    f2h_kernel<<<1024,  256>>>((const float4*)Wp,   (__half2*)wph,   262144);

    // 1) qkv = x @ W_qkv^T (fp16 out, phi fused on q,k)
    gemm_f16<true, false, true><<<dim3(24, 128), 256, SMEM_GEMM>>>(
        xh, wqkvh, nullptr, nullptr, qkvh, 16384, 3072, 1024);
    // 2) kv outer-product + k_sum partials, then reduce
    kv_partial_kernel<<<dim3(64, 8), 256>>>(qkvh, kvp, ksp);
    kv_reduce_kernel<<<64, 256>>>(kvp, ksp, kv, ks);
    // 3) normalize + q @ kv -> attn (fp16)
    attn_out_kernel<<<dim3(64, 8), 256>>>(qkvh, kv, ks, attnh);
    // 4) out = attn @ W_proj^T + b_proj (fp32 out)
    gemm_f16<false, true, false><<<dim3(8, 128), 256, SMEM_GEMM>>>(
        attnh, wph, bp, out, nullptr, 16384, 1024, 1024);
}